// round 5
// baseline (speedup 1.0000x reference)
#include <cuda_runtime.h>
#include <cstdint>

// Problem constants (fixed by setup_inputs): B=2, N=256, D=256, H=8, LEN=516
#define B_      2
#define N_      256
#define H_      8
#define ITEMS_  131072
#define LEN_    516
#define EPS_    1e-8f
#define TILE_   32
#define NTILES_ (ITEMS_ / TILE_)   // 4096
#define GRID_   304                // 2 persistent CTAs per SM

typedef unsigned long long u64;

// ---------------- device-global scratch (no allocation allowed) -------------
__device__ float g_scores[ITEMS_];
__device__ float g_ind[N_];

// dynamic smem per CTA:
//   4 stage-buffers [32 items x 33 chunks] u128  (67,584 B)
//   wbuf 1024 u128                               (16,384 B)
//   part [11][8][32] f32                         (11,264 B)
//   outs 256 f32                                 ( 1,024 B)
//   wts  40 f32
#define BUFCH_      (TILE_ * 33)
#define SMEM_TOTAL  ((4 * BUFCH_ + 1024) * 16 + 11 * 8 * TILE_ * 4 + 256 * 4 + 40 * 4)

// ---------------- packed f32x2 helpers (sm_103a) ----------------------------
__device__ __forceinline__ u64 ffma2(u64 a, u64 b, u64 c) {
    u64 d;
    asm("fma.rn.f32x2 %0, %1, %2, %3;" : "=l"(d) : "l"(a), "l"(b), "l"(c));
    return d;
}
__device__ __forceinline__ float hadd2(u64 v) {
    float lo, hi;
    asm("mov.b64 {%0, %1}, %2;" : "=f"(lo), "=f"(hi) : "l"(v));
    return lo + hi;
}

// ============================================================================
// cp.async stage copy: stage s = u128 chunks [s*16, s*16+16) of q and k.
//   buffer: item i (0..31) x chunk c (0..31) (+1 pad): c<16 -> q, else k.
//   thread t: c = t&31 fixed, item0 = t>>5, items item0 + 8j (j=0..3).
// ============================================================================
__device__ __forceinline__ void docopy(uint32_t d0, const ulonglong2* __restrict__ sb,
                                       long tile, int s, int item0, int c, int cc)
{
    const ulonglong2* src = sb + (tile * TILE_ + item0) * 64 + s * 16 + cc;
    uint32_t d = d0 + (uint32_t)((item0 * 33 + c) * 16);
#pragma unroll
    for (int j = 0; j < 4; j++) {
        asm volatile("cp.async.cg.shared.global [%0], [%1], 16;" :: "r"(d), "l"(src));
        src += 8 * 64;
        d   += 8 * 33 * 16;
    }
}

// ============================================================================
// Kernel 1 (fused): 2 CTAs/SM, 256 threads, TILE=32, 4-stage cp.async pipe.
//   Warp w owns chunks {2w, 2w+1} per stage; lane = item; 11 packed accs.
//   Weights gathered from W directly into smem (broadcast LDS thereafter).
// ============================================================================
__global__ __launch_bounds__(256, 2)
void fused_main(const ulonglong2* __restrict__ q2, const ulonglong2* __restrict__ k2,
                const float2* __restrict__ sq2, const float2* __restrict__ sk2,
                const float* __restrict__ roi, const float* __restrict__ W,
                const float* __restrict__ bias, float4* __restrict__ out4)
{
    extern __shared__ ulonglong2 smem[];
    ulonglong2* wbuf = smem + 4 * BUFCH_;            // 1024 u128 (16KB)
    float* part = (float*)(wbuf + 1024);             // [11][8][32]
    float* outs = part + 11 * 8 * TILE_;             // 256 floats
    float* wts  = outs + 256;                        // 32 tail + 8 bias

    const int t    = threadIdx.x;
    const int w    = t >> 5;
    const int lane = t & 31;

    // ---- gather permuted weights straight from W into smem ----
    // wbuf[g*16 + h*2 + half] = W[h][ half*256 + 4g .. +3 ]
    for (int i = t; i < 1024; i += 256) {
        const int g = i >> 4, h = (i >> 1) & 7, half = i & 1;
        const float4 v = *(const float4*)(W + h * LEN_ + half * 256 + g * 4);
        wbuf[i - (i & 15) + ((i & 15))] = *(const ulonglong2*)&v;   // wbuf[i]
    }
    if (t < 32) wts[t]      = W[(t >> 2) * LEN_ + 512 + (t & 3)];
    if (t < 8)  wts[32 + t] = bias[t];

    // copy geometry (constant per thread)
    const int c     = t & 31;
    const int item0 = t >> 5;
    const int cc    = c & 15;
    const ulonglong2* sb = (c < 16) ? q2 : k2;
    uint32_t bad[4];
#pragma unroll
    for (int s = 0; s < 4; s++)
        bad[s] = (uint32_t)__cvta_generic_to_shared(smem + s * BUFCH_);

    u64 acc[11];

    auto compute = [&](int s) {
        const ulonglong2* da = smem + s * BUFCH_ + lane * 33;
#pragma unroll
        for (int j = 0; j < 2; j++) {
            const int cq = w * 2 + j;
            const ulonglong2 qa = da[cq], ka = da[16 + cq];
            const ulonglong2* wp = wbuf + (s * 16 + cq) * 16;
#pragma unroll
            for (int h = 0; h < 8; h++) {
                const ulonglong2 wq = wp[h * 2];
                const ulonglong2 wk = wp[h * 2 + 1];
                acc[h] = ffma2(qa.x, wq.x, acc[h]);
                acc[h] = ffma2(qa.y, wq.y, acc[h]);
                acc[h] = ffma2(ka.x, wk.x, acc[h]);
                acc[h] = ffma2(ka.y, wk.y, acc[h]);
            }
            acc[8]  = ffma2(qa.x, ka.x, acc[8]);  acc[8]  = ffma2(qa.y, ka.y, acc[8]);
            acc[9]  = ffma2(qa.x, qa.x, acc[9]);  acc[9]  = ffma2(qa.y, qa.y, acc[9]);
            acc[10] = ffma2(ka.x, ka.x, acc[10]); acc[10] = ffma2(ka.y, ka.y, acc[10]);
        }
    };

    // prologue: fill the 4 stage buffers with the first tile's stages
    long tile = blockIdx.x;
#pragma unroll
    for (int s = 0; s < 4; s++) {
        if (tile < NTILES_) docopy(bad[s], sb, tile, s, item0, c, cc);
        asm volatile("cp.async.commit_group;");
    }

    for (; tile < NTILES_; tile += GRID_) {
        const long tn = tile + GRID_;
#pragma unroll
        for (int v = 0; v < 11; v++) acc[v] = 0ull;

#pragma unroll
        for (int s = 0; s < 4; s++) {
            asm volatile("cp.async.wait_group 3;");
            __syncthreads();                           // buffer s ready & visible
            compute(s);
            if (s == 3) {
#pragma unroll
                for (int v = 0; v < 11; v++)
                    part[(v * 8 + w) * TILE_ + lane] = hadd2(acc[v]);
            }
            __syncthreads();                           // done reading buffer s
            if (tn < NTILES_) docopy(bad[s], sb, tn, s, item0, c, cc);
            asm volatile("cp.async.commit_group;");
        }

        // ---- epilogue: heads (warp h handles head h, lane = item) ----
        {
            const int it = lane;
            float sacc = 0.f;
#pragma unroll
            for (int w2 = 0; w2 < 8; w2++) sacc += part[(w * 8 + w2) * TILE_ + it];
            const int ig = (int)tile * TILE_ + it;
            const float4 wt = *(const float4*)(wts + w * 4);
            const float2 a  = sq2[ig];
            const float2 bb = sk2[ig];
            const float pre = sacc + a.x * wt.x + a.y * wt.y
                                   + bb.x * wt.z + bb.y * wt.w + wts[32 + w];
            outs[it * 8 + w] = (1.0f / (1.0f + __expf(-pre))) * roi[ig];
        }
        // ---- epilogue: cosine (threads 0..31) ----
        if (t < 32) {
            float qk = 0.f, qq = 0.f, kk = 0.f;
#pragma unroll
            for (int w2 = 0; w2 < 8; w2++) {
                qk += part[(8  * 8 + w2) * TILE_ + t];
                qq += part[(9  * 8 + w2) * TILE_ + t];
                kk += part[(10 * 8 + w2) * TILE_ + t];
            }
            const float qn = fmaxf(sqrtf(qq), EPS_);
            const float kn = fmaxf(sqrtf(kk), EPS_);
            g_scores[(int)tile * TILE_ + t] = fmaxf(qk / (qn * kn), 0.0f);
        }
        __syncthreads();                               // outs ready
        if (t < 64) out4[tile * 64 + t] = ((const float4*)outs)[t];
    }
}

// ============================================================================
// Kernel 2a: zero the indicator (tiny)
// ============================================================================
__global__ void zero_ind()
{
    if (threadIdx.x < N_) g_ind[threadIdx.x] = 0.0f;
}

// ============================================================================
// Kernel 2b: warp-per-row exact top-k marking via 32-bit radix select.
//   Selected(t) iff key_t > T, or key_t == T and cnt_gt + #{j<t: key_j==T} < nn
//   — exactly rank = #{>} + #{==, j<t} < nn (jax.lax.top_k semantics).
// ============================================================================
__global__ void mark_topk(const int* __restrict__ node_num_p)
{
    const int row  = (blockIdx.x * blockDim.x + threadIdx.x) >> 5;   // 0..511
    const int lane = threadIdx.x & 31;
    const int nn   = *node_num_p;

    const float4* rp = (const float4*)(g_scores + row * N_);
    const float4 v0 = rp[lane * 2];
    const float4 v1 = rp[lane * 2 + 1];
    unsigned key[8];
    key[0] = __float_as_uint(v0.x); key[1] = __float_as_uint(v0.y);
    key[2] = __float_as_uint(v0.z); key[3] = __float_as_uint(v0.w);
    key[4] = __float_as_uint(v1.x); key[5] = __float_as_uint(v1.y);
    key[6] = __float_as_uint(v1.z); key[7] = __float_as_uint(v1.w);

    unsigned prefix = 0, mask = 0;
    int k = nn;
#pragma unroll
    for (int b = 31; b >= 0; b--) {
        const unsigned bit = 1u << b;
        const unsigned m = mask | bit, p = prefix | bit;
        int cl = 0;
#pragma unroll
        for (int i = 0; i < 8; i++) cl += ((key[i] & m) == p);
        const int cnt = __reduce_add_sync(0xffffffffu, cl);
        if (cnt >= k) prefix = p; else k -= cnt;
        mask = m;
    }
    const unsigned T = prefix;
    const int cnt_gt = nn - k;

    int eqc = 0;
#pragma unroll
    for (int i = 0; i < 8; i++) eqc += (key[i] == T);
    int ex = eqc;
#pragma unroll
    for (int o = 1; o < 32; o <<= 1) {
        const int nb = __shfl_up_sync(0xffffffffu, ex, o);
        if (lane >= o) ex += nb;
    }
    ex -= eqc;

    int run = cnt_gt + ex;
#pragma unroll
    for (int i = 0; i < 8; i++) {
        const bool eq = (key[i] == T);
        if ((key[i] > T) || (eq && run < nn)) g_ind[lane * 8 + i] = 1.0f;
        run += eq;
    }
}

// ============================================================================
// Kernel 3: out[b,q,k,h] *= ind[k]  (1 float4/thread, 262144 threads — enough
//   warps/SM to hide L2 latency; out is L2-resident after fused_main)
// ============================================================================
__global__ void apply_ind(float4* __restrict__ out4)
{
    const int i4  = blockIdx.x * blockDim.x + threadIdx.x;  // 0..262143
    const float m = g_ind[(i4 >> 1) & (N_ - 1)];
    float4 v = out4[i4];
    v.x *= m; v.y *= m; v.z *= m; v.w *= m;
    out4[i4] = v;
}

// ============================================================================
extern "C" void kernel_launch(void* const* d_in, const int* in_sizes, int n_in,
                              void* d_out, int out_size)
{
    (void)in_sizes; (void)n_in; (void)out_size;
    const ulonglong2* q2  = (const ulonglong2*)d_in[0];
    const ulonglong2* k2  = (const ulonglong2*)d_in[1];
    const float2*     sq  = (const float2*)d_in[2];
    const float2*     sk  = (const float2*)d_in[3];
    const float*      roi = (const float*)d_in[4];
    const float*      W   = (const float*)d_in[5];
    const float*      b   = (const float*)d_in[6];
    const int*        nn  = (const int*)d_in[7];
    float4* out4 = (float4*)d_out;

    cudaFuncSetAttribute(fused_main, cudaFuncAttributeMaxDynamicSharedMemorySize,
                         SMEM_TOTAL);

    zero_ind<<<1, 256>>>();
    fused_main<<<GRID_, 256, SMEM_TOTAL>>>(q2, k2, sq, sk, roi, W, b, out4);
    mark_topk<<<64, 256>>>(nn);
    apply_ind<<<1024, 256>>>(out4);
}

// round 6
// speedup vs baseline: 1.3137x; 1.3137x over previous
#include <cuda_runtime.h>
#include <cstdint>

// Problem constants (fixed by setup_inputs): B=2, N=256, D=256, H=8, LEN=516
#define B_      2
#define N_      256
#define H_      8
#define ITEMS_  131072
#define LEN_    516
#define EPS_    1e-8f
#define TILE_   64
#define NTILES_ (ITEMS_ / TILE_)   // 2048
#define GRID_   304                // 2 persistent CTAs per SM

typedef unsigned long long u64;

// ---------------- device-global scratch (no allocation allowed) -------------
__device__ float g_scores[ITEMS_];
__device__ float g_ind[N_];

// dynamic smem per CTA:
//   4 stage buffers [64 items x 17 u128] = 4*17408 B   (69,632)
//   wbuf 1024 u128                                      (16,384)
//   part [11][8][64] f32                                (22,528)
//   outs 512 f32                                        ( 2,048)
//   wts  40 f32                                         (   160)
#define BUFU_       (TILE_ * 17)                 // 1088 u128
#define SMEM_TOTAL  ((4 * BUFU_ + 1024) * 16 + 11 * 8 * 64 * 4 + 512 * 4 + 40 * 4)

// ---------------- packed f32x2 helpers (sm_103a) ----------------------------
__device__ __forceinline__ u64 ffma2(u64 a, u64 b, u64 c) {
    u64 d;
    asm("fma.rn.f32x2 %0, %1, %2, %3;" : "=l"(d) : "l"(a), "l"(b), "l"(c));
    return d;
}
__device__ __forceinline__ float hadd2(u64 v) {
    float lo, hi;
    asm("mov.b64 {%0, %1}, %2;" : "=f"(lo), "=f"(hi) : "l"(v));
    return lo + hi;
}

// ============================================================================
// cp.async stage copy: stage s = u128 chunks [s*8, s*8+8) of q and k.
//   buffer: item i (0..63) x chunk c (0..16): c<8 -> q chunk c, c in 8..15 ->
//   k chunk c-8, c=16 pad. thread t: c = t&15, item0 = t>>4, items item0+16j.
// ============================================================================
__device__ __forceinline__ void docopy(uint32_t dbase, const ulonglong2* __restrict__ sb,
                                       long tile, int s, int item0, int cc, uint32_t dcon)
{
    const ulonglong2* src = sb + (tile * TILE_ + item0) * 64 + s * 8 + cc;
    uint32_t d = dbase + dcon;
#pragma unroll
    for (int j = 0; j < 4; j++) {
        asm volatile("cp.async.cg.shared.global [%0], [%1], 16;" :: "r"(d), "l"(src));
        src += 16 * 64;          // 16 items forward
        d   += 16 * 17 * 16;     // 16 padded rows
    }
}

// ============================================================================
// Kernel 1 (fused): 2 CTAs/SM, 256 threads, TILE=64, 8 stages x 32 channels,
//   4-buffer ring, lookahead-3 (wait_group 2), ONE barrier per stage.
//   Warp w owns chunk-pair w; lane handles items lane and lane+32 (2 items ->
//   weight broadcasts amortized). 22 packed accumulators.
// ============================================================================
__global__ __launch_bounds__(256, 2)
void fused_main(const ulonglong2* __restrict__ q2, const ulonglong2* __restrict__ k2,
                const float2* __restrict__ sq2, const float2* __restrict__ sk2,
                const float* __restrict__ roi, const float* __restrict__ W,
                const float* __restrict__ bias, float4* __restrict__ out4)
{
    extern __shared__ ulonglong2 smem[];
    ulonglong2* wbuf = smem + 4 * BUFU_;             // 1024 u128 (16KB)
    float* part = (float*)(wbuf + 1024);             // [11][8][64]
    float* outs = part + 11 * 8 * 64;                // 512 floats
    float* wts  = outs + 512;                        // 32 tail + 8 bias

    const int t    = threadIdx.x;
    const int w    = t >> 5;
    const int lane = t & 31;

    // ---- gather permuted weights from W into smem (wbuf[g*16+h*2+half]) ----
    for (int i = t; i < 1024; i += 256) {
        const int g = i >> 4, h = (i >> 1) & 7, half = i & 1;
        const float4 v = *(const float4*)(W + h * LEN_ + half * 256 + g * 4);
        wbuf[i] = *(const ulonglong2*)&v;
    }
    if (t < 32) wts[t]      = W[(t >> 2) * LEN_ + 512 + (t & 3)];
    if (t < 8)  wts[32 + t] = bias[t];

    // copy geometry (constant per thread)
    const int c     = t & 15;
    const int item0 = t >> 4;
    const int cc    = c & 7;
    const ulonglong2* sb = (c < 8) ? q2 : k2;
    const uint32_t dcon = (uint32_t)((item0 * 17 + c) * 16);
    uint32_t bad[4];
#pragma unroll
    for (int s = 0; s < 4; s++)
        bad[s] = (uint32_t)__cvta_generic_to_shared(smem + s * BUFU_);

    u64 acc[22];

    // prologue: stream stages 0,1,2 of first tile (3 groups in flight)
    long tile = blockIdx.x;
#pragma unroll
    for (int s = 0; s < 3; s++) {
        docopy(bad[s], sb, tile, s, item0, cc, dcon);
        asm volatile("cp.async.commit_group;");
    }

    for (; tile < NTILES_; tile += GRID_) {
#pragma unroll
        for (int v = 0; v < 22; v++) acc[v] = 0ull;
        float2 sqa, sqb, ska, skb; float ra, rb;

#pragma unroll
        for (int s = 0; s < 8; s++) {
            asm volatile("cp.async.wait_group 2;");
            __syncthreads();                         // stage s data ready+visible;
                                                     // everyone done with stage s-1
            // refill stream stage s+3 -> buffer (s+3)&3 (holds s-1's data: safe)
            {
                int  rs = s + 3;
                long rt = tile;
                if (rs >= 8) { rs -= 8; rt += GRID_; }
                if (rt < NTILES_) docopy(bad[(s + 3) & 3], sb, rt, rs, item0, cc, dcon);
                asm volatile("cp.async.commit_group;");
            }
            if (s == 0) {                            // prefetch epilogue operands
                const int ig = (int)tile * TILE_ + lane;
                sqa = sq2[ig];       ska = sk2[ig];       ra = roi[ig];
                sqb = sq2[ig + 32];  skb = sk2[ig + 32];  rb = roi[ig + 32];
            }
            // ---- compute stage s from buffer s&3 ----
            {
                const ulonglong2* da = smem + (s & 3) * BUFU_ + lane * 17;
                const ulonglong2* db = da + 32 * 17;
                const ulonglong2 qa = da[w], ka = da[8 + w];
                const ulonglong2 qb = db[w], kb = db[8 + w];
                const ulonglong2* wp = wbuf + (s * 8 + w) * 16;
#pragma unroll
                for (int h = 0; h < 8; h++) {
                    const ulonglong2 wq = wp[h * 2];
                    const ulonglong2 wk = wp[h * 2 + 1];
                    acc[h] = ffma2(qa.x, wq.x, acc[h]);
                    acc[h] = ffma2(qa.y, wq.y, acc[h]);
                    acc[h] = ffma2(ka.x, wk.x, acc[h]);
                    acc[h] = ffma2(ka.y, wk.y, acc[h]);
                    acc[11 + h] = ffma2(qb.x, wq.x, acc[11 + h]);
                    acc[11 + h] = ffma2(qb.y, wq.y, acc[11 + h]);
                    acc[11 + h] = ffma2(kb.x, wk.x, acc[11 + h]);
                    acc[11 + h] = ffma2(kb.y, wk.y, acc[11 + h]);
                }
                acc[8]  = ffma2(qa.x, ka.x, acc[8]);  acc[8]  = ffma2(qa.y, ka.y, acc[8]);
                acc[9]  = ffma2(qa.x, qa.x, acc[9]);  acc[9]  = ffma2(qa.y, qa.y, acc[9]);
                acc[10] = ffma2(ka.x, ka.x, acc[10]); acc[10] = ffma2(ka.y, ka.y, acc[10]);
                acc[19] = ffma2(qb.x, kb.x, acc[19]); acc[19] = ffma2(qb.y, kb.y, acc[19]);
                acc[20] = ffma2(qb.x, qb.x, acc[20]); acc[20] = ffma2(qb.y, qb.y, acc[20]);
                acc[21] = ffma2(kb.x, kb.x, acc[21]); acc[21] = ffma2(kb.y, kb.y, acc[21]);
            }
        }

        // ---- partials ----
#pragma unroll
        for (int v = 0; v < 11; v++) {
            part[(v * 8 + w) * 64 + lane]      = hadd2(acc[v]);
            part[(v * 8 + w) * 64 + 32 + lane] = hadd2(acc[11 + v]);
        }
        __syncthreads();

        // ---- epilogue: heads (warp w = head w; items lane, lane+32) ----
        {
            float s1 = 0.f, s2 = 0.f;
#pragma unroll
            for (int w2 = 0; w2 < 8; w2++) {
                s1 += part[(w * 8 + w2) * 64 + lane];
                s2 += part[(w * 8 + w2) * 64 + 32 + lane];
            }
            const float4 wt = *(const float4*)(wts + w * 4);
            const float bb = wts[32 + w];
            const float p1 = s1 + sqa.x * wt.x + sqa.y * wt.y
                                + ska.x * wt.z + ska.y * wt.w + bb;
            const float p2 = s2 + sqb.x * wt.x + sqb.y * wt.y
                                + skb.x * wt.z + skb.y * wt.w + bb;
            outs[lane * 8 + w]        = (1.0f / (1.0f + __expf(-p1))) * ra;
            outs[(lane + 32) * 8 + w] = (1.0f / (1.0f + __expf(-p2))) * rb;
        }
        // ---- epilogue: cosine (threads 0..63, item = t) ----
        if (t < 64) {
            float qk = 0.f, qq = 0.f, kk = 0.f;
#pragma unroll
            for (int w2 = 0; w2 < 8; w2++) {
                qk += part[(8  * 8 + w2) * 64 + t];
                qq += part[(9  * 8 + w2) * 64 + t];
                kk += part[(10 * 8 + w2) * 64 + t];
            }
            const float qn = fmaxf(sqrtf(qq), EPS_);
            const float kn = fmaxf(sqrtf(kk), EPS_);
            g_scores[(int)tile * TILE_ + t] = fmaxf(qk / (qn * kn), 0.0f);
        }
        __syncthreads();                             // outs ready
        if (t < 128) out4[tile * 128 + t] = ((const float4*)outs)[t];
    }
}

// ============================================================================
// Kernel 2a: zero the indicator
// ============================================================================
__global__ void zero_ind()
{
    if (threadIdx.x < N_) g_ind[threadIdx.x] = 0.0f;
}

// ============================================================================
// Kernel 2b: warp-per-row exact top-k marking via 32-bit radix select.
//   Selected(t) iff key_t > T, or key_t == T and cnt_gt + #{j<t: key_j==T} < nn
//   — exactly rank = #{>} + #{==, j<t} < nn (jax.lax.top_k semantics).
// ============================================================================
__global__ void mark_topk(const int* __restrict__ node_num_p)
{
    const int row  = (blockIdx.x * blockDim.x + threadIdx.x) >> 5;   // 0..511
    const int lane = threadIdx.x & 31;
    const int nn   = *node_num_p;

    const float4* rp = (const float4*)(g_scores + row * N_);
    const float4 v0 = rp[lane * 2];
    const float4 v1 = rp[lane * 2 + 1];
    unsigned key[8];
    key[0] = __float_as_uint(v0.x); key[1] = __float_as_uint(v0.y);
    key[2] = __float_as_uint(v0.z); key[3] = __float_as_uint(v0.w);
    key[4] = __float_as_uint(v1.x); key[5] = __float_as_uint(v1.y);
    key[6] = __float_as_uint(v1.z); key[7] = __float_as_uint(v1.w);

    unsigned prefix = 0, mask = 0;
    int k = nn;
#pragma unroll
    for (int b = 31; b >= 0; b--) {
        const unsigned bit = 1u << b;
        const unsigned m = mask | bit, p = prefix | bit;
        int cl = 0;
#pragma unroll
        for (int i = 0; i < 8; i++) cl += ((key[i] & m) == p);
        const int cnt = __reduce_add_sync(0xffffffffu, cl);
        if (cnt >= k) prefix = p; else k -= cnt;
        mask = m;
    }
    const unsigned T = prefix;
    const int cnt_gt = nn - k;

    int eqc = 0;
#pragma unroll
    for (int i = 0; i < 8; i++) eqc += (key[i] == T);
    int ex = eqc;
#pragma unroll
    for (int o = 1; o < 32; o <<= 1) {
        const int nb = __shfl_up_sync(0xffffffffu, ex, o);
        if (lane >= o) ex += nb;
    }
    ex -= eqc;

    int run = cnt_gt + ex;
#pragma unroll
    for (int i = 0; i < 8; i++) {
        const bool eq = (key[i] == T);
        if ((key[i] > T) || (eq && run < nn)) g_ind[lane * 8 + i] = 1.0f;
        run += eq;
    }
}

// ============================================================================
// Kernel 3: out *= ind[col]. 4 batched float4 per thread (MLP=4); offsets of
//   65536 float4 = 32768 items ≡ 0 mod 256 -> same indicator column.
// ============================================================================
__global__ void apply_ind(float4* __restrict__ out4)
{
    const int i = blockIdx.x * blockDim.x + threadIdx.x;   // 0..65535
    float4 v0 = out4[i];
    float4 v1 = out4[i + 65536];
    float4 v2 = out4[i + 131072];
    float4 v3 = out4[i + 196608];
    const float m = g_ind[(i >> 1) & (N_ - 1)];
    v0.x *= m; v0.y *= m; v0.z *= m; v0.w *= m;
    v1.x *= m; v1.y *= m; v1.z *= m; v1.w *= m;
    v2.x *= m; v2.y *= m; v2.z *= m; v2.w *= m;
    v3.x *= m; v3.y *= m; v3.z *= m; v3.w *= m;
    out4[i]          = v0;
    out4[i + 65536]  = v1;
    out4[i + 131072] = v2;
    out4[i + 196608] = v3;
}

// ============================================================================
extern "C" void kernel_launch(void* const* d_in, const int* in_sizes, int n_in,
                              void* d_out, int out_size)
{
    (void)in_sizes; (void)n_in; (void)out_size;
    const ulonglong2* q2  = (const ulonglong2*)d_in[0];
    const ulonglong2* k2  = (const ulonglong2*)d_in[1];
    const float2*     sq  = (const float2*)d_in[2];
    const float2*     sk  = (const float2*)d_in[3];
    const float*      roi = (const float*)d_in[4];
    const float*      W   = (const float*)d_in[5];
    const float*      b   = (const float*)d_in[6];
    const int*        nn  = (const int*)d_in[7];
    float4* out4 = (float4*)d_out;

    cudaFuncSetAttribute(fused_main, cudaFuncAttributeMaxDynamicSharedMemorySize,
                         SMEM_TOTAL);

    zero_ind<<<1, 256>>>();
    fused_main<<<GRID_, 256, SMEM_TOTAL>>>(q2, k2, sq, sk, roi, W, b, out4);
    mark_topk<<<64, 256>>>(nn);
    apply_ind<<<256, 256>>>(out4);
}